// round 16
// baseline (speedup 1.0000x reference)
#include <cuda_runtime.h>
#include <math.h>
#include <limits.h>
#include <stdint.h>

#define BB 8
#define KK 512
#define DD 16
#define MAX_CPN 512
#define CPBUF 1024
#define BG_W 2.0f

#define TPA 1024
#define TPC 512
#define PPC 4096
#define UC 4

// ---------------- device scratch (all-zero == clean state; finalize re-zeros) ----------------
__device__ int    g_cnt[BB*KK];
__device__ float  g_sumexp[BB*KK];
__device__ float  g_dsum[BB*KK];
__device__ int    g_cpcnt[BB*KK];
__device__ int    g_fimax[BB*KK];      // 0 = none, else (N - first_cp_index)
__device__ float  g_cpbeta[BB*KK];
__device__ float  g_ref[BB*KK*DD];
__device__ int    g_ncp[BB];
__device__ int    g_nbg[BB];
__device__ float  g_bgsig[BB];
__device__ int    g_cpidx[BB*CPBUF];
__device__ float  g_rep[BB];
__device__ float  g_batch[BB*5];
__device__ unsigned g_tick;

__device__ __forceinline__ float dist16(float4 a0, float4 a1, float4 a2, float4 a3,
                                        float4 b0, float4 b1, float4 b2, float4 b3) {
    float d = 0.f, df;
    df = a0.x-b0.x; d += df*df; df = a0.y-b0.y; d += df*df;
    df = a0.z-b0.z; d += df*df; df = a0.w-b0.w; d += df*df;
    df = a1.x-b1.x; d += df*df; df = a1.y-b1.y; d += df*df;
    df = a1.z-b1.z; d += df*df; df = a1.w-b1.w; d += df*df;
    df = a2.x-b2.x; d += df*df; df = a2.y-b2.y; d += df*df;
    df = a2.z-b2.z; d += df*df; df = a2.w-b2.w; d += df*df;
    df = a3.x-b3.x; d += df*df; df = a3.y-b3.y; d += df*df;
    df = a3.z-b3.z; d += df*df; df = a3.w-b3.w; d += df*df;
    return d;
}

// ---------------- pass A: light stats + cnt/sumexp shared histograms (wide blocks) ----------------
__global__ void __launch_bounds__(TPA)
pass_a(const float* __restrict__ beta, const int* __restrict__ sid,
       const int* __restrict__ iscp, int N) {
    __shared__ int   s_cnt[KK];
    __shared__ float s_sx[KK];
    __shared__ float sw[32];
    __shared__ int   swc[32];
    int b = blockIdx.y;
    int t = threadIdx.x;
    if (t < KK) { s_cnt[t] = 0; s_sx[t] = 0.f; }
    __syncthreads();

    const int4*   s4p = (const int4*)(sid  + (size_t)b * N);
    const int4*   c4p = (const int4*)(iscp + (size_t)b * N);
    const float4* b4p = (const float4*)(beta + (size_t)b * N);
    int NG = N >> 2;
    int gt = blockIdx.x * TPA + t;
    int G  = gridDim.x * TPA;
    float bgs = 0.f; int bgc = 0;

    for (int j = gt; j < NG; j += G) {
        int4   s4 = s4p[j];
        int4   c4 = c4p[j];
        float4 bt = b4p[j];
        int   ss[4] = { s4.x, s4.y, s4.z, s4.w };
        int   cc[4] = { c4.x, c4.y, c4.z, c4.w };
        float bv[4] = { bt.x, bt.y, bt.z, bt.w };
        int bi = j << 2;
        #pragma unroll
        for (int e = 0; e < 4; e++) {
            int s = ss[e];
            if (s < 0) {
                bgc++; bgs += 1.f / (1.f + __expf(-bv[e]));
            } else {
                atomicAdd(&s_cnt[s], 1);
                atomicAdd(&s_sx[s], __expf(bv[e]));
            }
            if (cc[e] == 1) {
                if (s >= 0) {
                    int gi = b*KK + s;
                    atomicAdd(&g_cpcnt[gi], 1);
                    atomicAdd(&g_cpbeta[gi], bv[e]);
                    atomicMax(&g_fimax[gi], N - (bi + e));
                }
                int pos = atomicAdd(&g_ncp[b], 1);
                if (pos < CPBUF) g_cpidx[b*CPBUF + pos] = bi + e;
            }
        }
    }
    for (int i = (NG << 2) + gt; i < N; i += G) {   // tail
        int s = sid[(size_t)b*N + i];
        int c = iscp[(size_t)b*N + i];
        float btv = beta[(size_t)b*N + i];
        if (s < 0) {
            bgc++; bgs += 1.f / (1.f + __expf(-btv));
        } else {
            atomicAdd(&s_cnt[s], 1);
            atomicAdd(&s_sx[s], __expf(btv));
        }
        if (c == 1) {
            if (s >= 0) {
                int gi = b*KK + s;
                atomicAdd(&g_cpcnt[gi], 1);
                atomicAdd(&g_cpbeta[gi], btv);
                atomicMax(&g_fimax[gi], N - i);
            }
            int pos = atomicAdd(&g_ncp[b], 1);
            if (pos < CPBUF) g_cpidx[b*CPBUF + pos] = i;
        }
    }
    for (int o = 16; o > 0; o >>= 1) {
        bgs += __shfl_down_sync(0xffffffffu, bgs, o);
        bgc += __shfl_down_sync(0xffffffffu, bgc, o);
    }
    if ((t & 31) == 0) { sw[t >> 5] = bgs; swc[t >> 5] = bgc; }
    __syncthreads();
    if (t < 32) {
        float v = sw[t]; int c = swc[t];
        for (int o = 16; o > 0; o >>= 1) {
            v += __shfl_down_sync(0xffffffffu, v, o);
            c += __shfl_down_sync(0xffffffffu, c, o);
        }
        if (t == 0 && c > 0) { atomicAdd(&g_bgsig[b], v); atomicAdd(&g_nbg[b], c); }
    }
    __syncthreads();
    if (t < KK) {
        int c = s_cnt[t];
        if (c > 0) {
            atomicAdd(&g_cnt[b*KK + t], c);
            atomicAdd(&g_sumexp[b*KK + t], s_sx[t]);
        }
    }
}

// ---------------- pass B: gather reference embeddings ----------------
__global__ void __launch_bounds__(512)
gather_ref(const float* __restrict__ embed, int N) {
    int gt = blockIdx.x * 512 + threadIdx.x;
    if (gt >= BB*KK*4) return;
    int gi = gt >> 2, comp = gt & 3;
    int b = gi >> 9;
    int fm = g_fimax[gi];
    float4 v = make_float4(0.f, 0.f, 0.f, 0.f);
    if (fm > 0)
        v = ((const float4*)(embed + (size_t)b*N*DD))[(size_t)(N - fm) * 4 + comp];
    ((float4*)g_ref)[gi*4 + comp] = v;
}

// ---------------- pass C (quad-split, 512 threads) + fused repulsion ----------------
__global__ void __launch_bounds__(TPC)
pass_c(const float* __restrict__ embed, const int* __restrict__ sid, int N, int NC) {
    __shared__ float4 s_tab[KK*4];   // 32 KB
    int b = blockIdx.y;
    int t = threadIdx.x;

    if (blockIdx.x < NC) {
        // ----- main embed stream -----
        const float4* gr = (const float4*)&g_ref[(size_t)b*KK*DD];
        for (int k = t; k < KK*4; k += TPC) s_tab[k] = gr[k];
        __syncthreads();

        const int*    sidB = sid + (size_t)b * N;
        const float4* ef4  = (const float4*)(embed + (size_t)b * N * DD);
        float* dsB = &g_dsum[b*KK];

        int base = blockIdx.x * PPC;
        int end  = min(base + PPC, N);
        int q = t >> 2;       // point-in-group 0..127
        int c = t & 3;        // component quad lane

        for (int i0 = base + q; i0 < end; i0 += 128 * UC) {
            int s[UC]; float4 e[UC];
            #pragma unroll
            for (int u = 0; u < UC; u++) {
                int i = i0 + u * 128;
                bool act = i < end;
                s[u] = act ? sidB[i] : -1;
                e[u] = act ? ef4[(size_t)i * 4 + c] : make_float4(0.f,0.f,0.f,0.f);
            }
            #pragma unroll
            for (int u = 0; u < UC; u++) {
                int ui = max(s[u], 0);
                float4 r = s_tab[(ui << 2) | c];
                float df, pd = 0.f;
                df = e[u].x - r.x; pd += df*df;
                df = e[u].y - r.y; pd += df*df;
                df = e[u].z - r.z; pd += df*df;
                df = e[u].w - r.w; pd += df*df;
                pd += __shfl_xor_sync(0xffffffffu, pd, 1);
                pd += __shfl_xor_sync(0xffffffffu, pd, 2);
                if (c == 0 && s[u] >= 0) atomicAdd(&dsB[s[u]], pd);
            }
        }
    } else {
        // ----- repulsion: 1 block per batch, 1 thread per cp point -----
        int P = g_ncp[b]; if (P > MAX_CPN) P = MAX_CPN;
        const float4* embB = (const float4*)(embed + (size_t)b * N * DD);
        for (int k = t; k < KK*4; k += TPC) {
            int jj = k >> 2;
            float4 v = make_float4(0.f, 0.f, 0.f, 0.f);
            if (jj < P) v = embB[(size_t)g_cpidx[b*CPBUF + jj] * 4 + (k & 3)];
            s_tab[k] = v;
        }
        __syncthreads();

        float acc = 0.f;
        if (t < P) {
            float4 a0 = s_tab[t*4+0], a1 = s_tab[t*4+1], a2 = s_tab[t*4+2], a3 = s_tab[t*4+3];
            #pragma unroll 2
            for (int j = 0; j < P; j++) {
                float d = dist16(a0, a1, a2, a3,
                                 s_tab[j*4+0], s_tab[j*4+1], s_tab[j*4+2], s_tab[j*4+3]);
                if (d < 30.f) acc += __expf(-d);   // exp(-30)~9e-14 negligible
            }
        }
        for (int o = 16; o > 0; o >>= 1) acc += __shfl_down_sync(0xffffffffu, acc, o);
        __shared__ float wsum[16];
        if ((t & 31) == 0) wsum[t >> 5] = acc;
        __syncthreads();
        if (t < 16) {
            float v = wsum[t];
            for (int o = 8; o > 0; o >>= 1) v += __shfl_down_sync(0xffffu, v, o);
            if (t == 0 && v != 0.f) atomicAdd(&g_rep[b], v);
        }
    }
}

// ---------------- finalize: 1 block per batch + ticket-based combine ----------------
__global__ void __launch_bounds__(512)
finalize_kernel(float* __restrict__ out, int out_size) {
    int b = blockIdx.x;
    int t = threadIdx.x;
    int lane = t & 31, warp = t >> 5;
    __shared__ float s_rce[16], s_rat[16];
    __shared__ int   s_rvl[16];
    __shared__ bool  s_last;

    int gi = b * KK + t;          // one segment per thread
    int   cnt = g_cnt[gi];
    float sx  = g_sumexp[gi];
    float ds  = g_dsum[gi];
    int   cpc = g_cpcnt[gi];
    float cpb = g_cpbeta[gi];
    float ce = 0.f, at = 0.f; int vl = 0;
    if (cnt > 0 && cpc == 1) { ce = __logf(fmaxf(sx, 1e-30f)) - cpb; vl = 1; }
    if (cnt > 0 && cpc >= 1)   at = __fdividef(ds, fmaxf((float)cnt, 1.f));

    // reset scratch slice for next graph replay
    g_cnt[gi] = 0; g_sumexp[gi] = 0.f; g_dsum[gi] = 0.f;
    g_cpcnt[gi] = 0; g_cpbeta[gi] = 0.f; g_fimax[gi] = 0;

    #pragma unroll
    for (int o = 16; o > 0; o >>= 1) {
        ce += __shfl_down_sync(0xffffffffu, ce, o);
        at += __shfl_down_sync(0xffffffffu, at, o);
        vl += __shfl_down_sync(0xffffffffu, vl, o);
    }
    if (lane == 0) { s_rce[warp] = ce; s_rat[warp] = at; s_rvl[warp] = vl; }
    __syncthreads();
    if (t == 0) {
        float c2 = 0.f, a2 = 0.f; int v2 = 0;
        #pragma unroll
        for (int w = 0; w < 16; w++) { c2 += s_rce[w]; a2 += s_rat[w]; v2 += s_rvl[w]; }
        float bl = c2 / fmaxf((float)v2, 1.f);
        float nbg = (float)g_nbg[b];
        if (nbg > 0.f) bl += BG_W * (g_bgsig[b] / nbg);
        float ncp = (float)g_ncp[b];
        float rep = (ncp > 1.f) ? g_rep[b] / fmaxf(ncp * ncp, 1.f) : 0.f;
        g_batch[b*5 + 0] = bl + a2 + rep;
        g_batch[b*5 + 1] = bl;
        g_batch[b*5 + 2] = a2;
        g_batch[b*5 + 3] = rep;
        g_batch[b*5 + 4] = (v2 > 0) ? 1.f : 0.f;
        g_ncp[b] = 0; g_nbg[b] = 0; g_bgsig[b] = 0.f; g_rep[b] = 0.f;
        __threadfence();
        unsigned tk = atomicAdd(&g_tick, 1u);
        s_last = (tk == BB - 1);
    }
    __syncthreads();
    if (s_last && t == 0) {
        __threadfence();
        float cnt2 = 0.f, t0 = 0.f, t1 = 0.f, t2 = 0.f, t3 = 0.f;
        for (int bb = 0; bb < BB; bb++) {
            float inc = g_batch[bb*5 + 4];
            cnt2 += inc;
            t0 += g_batch[bb*5 + 0] * inc;
            t1 += g_batch[bb*5 + 1] * inc;
            t2 += g_batch[bb*5 + 2] * inc;
            t3 += g_batch[bb*5 + 3] * inc;
        }
        float den = fmaxf(cnt2, 1.f);
        if (out_size > 0) out[0] = (cnt2 > 0.f) ? t0 / den : 0.f;
        if (out_size > 1) out[1] = t1 / den;
        if (out_size > 2) out[2] = t2 / den;
        if (out_size > 3) out[3] = t3 / den;
        g_tick = 0u;
    }
}

extern "C" void kernel_launch(void* const* d_in, const int* in_sizes, int n_in,
                              void* d_out, int out_size) {
    const float* beta  = (const float*)d_in[0];
    const float* embed = (const float*)d_in[1];
    const int*   sid   = (const int*)d_in[2];
    const int*   iscp  = (const int*)d_in[3];
    int N = in_sizes[0] / BB;

    dim3 ga(24, BB);
    pass_a<<<ga, TPA>>>(beta, sid, iscp, N);
    gather_ref<<<(BB*KK*4 + 511) / 512, 512>>>(embed, N);
    int NC = (N + PPC - 1) / PPC;
    dim3 gc(NC + 1, BB);
    pass_c<<<gc, TPC>>>(embed, sid, N, NC);
    finalize_kernel<<<BB, 512>>>((float*)d_out, out_size);
}

// round 17
// speedup vs baseline: 1.1845x; 1.1845x over previous
#include <cuda_runtime.h>
#include <math.h>
#include <limits.h>
#include <stdint.h>

#define BB 8
#define KK 512
#define DD 16
#define MAX_CPN 512
#define CPBUF 1024
#define BG_W 2.0f

#define TPB 256
#define PPC 2048
#define UC 4

// ---------------- device scratch (all-zero == clean state; finalize re-zeros) ----------------
__device__ float4 g_acc[BB*KK];        // {cnt, sumexp, dsum, pad}
__device__ int    g_cpcnt[BB*KK];
__device__ int    g_fimax[BB*KK];      // 0 = none, else (N - first_cp_index)
__device__ float  g_cpbeta[BB*KK];
__device__ float  g_ref[BB*KK*DD];
__device__ int    g_ncp[BB];
__device__ int    g_nbg[BB];
__device__ float  g_bgsig[BB];
__device__ int    g_cpidx[BB*CPBUF];
__device__ float  g_rep[BB];
__device__ float  g_batch[BB*5];
__device__ unsigned g_tick;

__device__ __forceinline__ float dist16(float4 a0, float4 a1, float4 a2, float4 a3,
                                        float4 b0, float4 b1, float4 b2, float4 b3) {
    float d = 0.f, df;
    df = a0.x-b0.x; d += df*df; df = a0.y-b0.y; d += df*df;
    df = a0.z-b0.z; d += df*df; df = a0.w-b0.w; d += df*df;
    df = a1.x-b1.x; d += df*df; df = a1.y-b1.y; d += df*df;
    df = a1.z-b1.z; d += df*df; df = a1.w-b1.w; d += df*df;
    df = a2.x-b2.x; d += df*df; df = a2.y-b2.y; d += df*df;
    df = a2.z-b2.z; d += df*df; df = a2.w-b2.w; d += df*df;
    df = a3.x-b3.x; d += df*df; df = a3.y-b3.y; d += df*df;
    df = a3.z-b3.z; d += df*df; df = a3.w-b3.w; d += df*df;
    return d;
}

// ---------------- pass A: light-array stats only (R6-proven) ----------------
__global__ void __launch_bounds__(TPB)
pass_a(const float* __restrict__ beta, const int* __restrict__ sid,
       const int* __restrict__ iscp, int N) {
    int b = blockIdx.y;
    const int4*   s4p = (const int4*)(sid  + (size_t)b * N);
    const int4*   c4p = (const int4*)(iscp + (size_t)b * N);
    const float4* b4p = (const float4*)(beta + (size_t)b * N);
    int NG = N >> 2;
    int gt = blockIdx.x * TPB + threadIdx.x;
    int G  = gridDim.x * TPB;
    float bgs = 0.f; int bgc = 0;

    for (int j = gt; j < NG; j += G) {
        int4   s4 = s4p[j];
        int4   c4 = c4p[j];
        float4 bt = b4p[j];
        int   ss[4] = { s4.x, s4.y, s4.z, s4.w };
        int   cc[4] = { c4.x, c4.y, c4.z, c4.w };
        float bv[4] = { bt.x, bt.y, bt.z, bt.w };
        int bi = j << 2;
        #pragma unroll
        for (int e = 0; e < 4; e++) {
            int s = ss[e];
            if (s < 0) { bgc++; bgs += 1.f / (1.f + __expf(-bv[e])); }
            if (cc[e] == 1) {
                if (s >= 0) {
                    int gi = b*KK + s;
                    atomicAdd(&g_cpcnt[gi], 1);
                    atomicAdd(&g_cpbeta[gi], bv[e]);
                    atomicMax(&g_fimax[gi], N - (bi + e));
                }
                int pos = atomicAdd(&g_ncp[b], 1);
                if (pos < CPBUF) g_cpidx[b*CPBUF + pos] = bi + e;
            }
        }
    }
    for (int i = (NG << 2) + gt; i < N; i += G) {   // tail
        int s = sid[(size_t)b*N + i];
        int c = iscp[(size_t)b*N + i];
        float btv = beta[(size_t)b*N + i];
        if (s < 0) { bgc++; bgs += 1.f / (1.f + __expf(-btv)); }
        if (c == 1) {
            if (s >= 0) {
                int gi = b*KK + s;
                atomicAdd(&g_cpcnt[gi], 1);
                atomicAdd(&g_cpbeta[gi], btv);
                atomicMax(&g_fimax[gi], N - i);
            }
            int pos = atomicAdd(&g_ncp[b], 1);
            if (pos < CPBUF) g_cpidx[b*CPBUF + pos] = i;
        }
    }
    for (int o = 16; o > 0; o >>= 1) {
        bgs += __shfl_down_sync(0xffffffffu, bgs, o);
        bgc += __shfl_down_sync(0xffffffffu, bgc, o);
    }
    if ((threadIdx.x & 31) == 0 && bgc > 0) {
        atomicAdd(&g_bgsig[b], bgs);
        atomicAdd(&g_nbg[b], bgc);
    }
}

// ---------------- pass B: gather reference embeddings ----------------
__global__ void __launch_bounds__(512)
gather_ref(const float* __restrict__ embed, int N) {
    int gt = blockIdx.x * 512 + threadIdx.x;
    if (gt >= BB*KK*4) return;
    int gi = gt >> 2, comp = gt & 3;
    int b = gi >> 9;
    int fm = g_fimax[gi];
    float4 v = make_float4(0.f, 0.f, 0.f, 0.f);
    if (fm > 0)
        v = ((const float4*)(embed + (size_t)b*N*DD))[(size_t)(N - fm) * 4 + comp];
    ((float4*)g_ref)[gi*4 + comp] = v;
}

// ---------------- pass C: quad-split, float4 RED (R6-proven) + fused repulsion ----------------
__global__ void __launch_bounds__(TPB)
pass_c(const float* __restrict__ beta, const float* __restrict__ embed,
       const int* __restrict__ sid, int N, int NC) {
    __shared__ float4 s_tab[KK*4];   // 32 KB
    int b = blockIdx.y;
    int t = threadIdx.x;

    if (blockIdx.x < NC) {
        // ----- main embed stream -----
        const float4* gr = (const float4*)&g_ref[(size_t)b*KK*DD];
        for (int k = t; k < KK*4; k += TPB) s_tab[k] = gr[k];
        __syncthreads();

        const float*  betB = beta  + (size_t)b * N;
        const int*    sidB = sid   + (size_t)b * N;
        const float4* ef4  = (const float4*)(embed + (size_t)b * N * DD);
        float4* accB = &g_acc[b*KK];

        int base = blockIdx.x * PPC;
        int end  = min(base + PPC, N);
        int q = t >> 2;       // point-in-group 0..63
        int c = t & 3;        // component quad lane

        for (int i0 = base + q; i0 < end; i0 += 64 * UC) {
            int s[UC]; float bt[UC]; float4 e[UC];
            #pragma unroll
            for (int u = 0; u < UC; u++) {
                int i = i0 + u * 64;
                bool act = i < end;
                s[u]  = act ? sidB[i] : -1;
                bt[u] = act ? betB[i] : 0.f;
                e[u]  = act ? ef4[(size_t)i * 4 + c] : make_float4(0.f,0.f,0.f,0.f);
            }
            #pragma unroll
            for (int u = 0; u < UC; u++) {
                int ui = max(s[u], 0);
                float4 r = s_tab[(ui << 2) | c];
                float df, pd = 0.f;
                df = e[u].x - r.x; pd += df*df;
                df = e[u].y - r.y; pd += df*df;
                df = e[u].z - r.z; pd += df*df;
                df = e[u].w - r.w; pd += df*df;
                pd += __shfl_xor_sync(0xffffffffu, pd, 1);
                pd += __shfl_xor_sync(0xffffffffu, pd, 2);
                float e0 = __expf(bt[u]);
                if (c == 0 && s[u] >= 0) {
                    atomicAdd(&accB[s[u]], make_float4(1.f, e0, pd, 0.f));
                }
            }
        }
    } else {
        // ----- repulsion: 2 blocks per batch, broadcast j-loop -----
        int half = blockIdx.x - NC;   // 0 or 1
        int P = g_ncp[b]; if (P > MAX_CPN) P = MAX_CPN;
        const float4* embB = (const float4*)(embed + (size_t)b * N * DD);
        for (int k = t; k < KK*4; k += TPB) {
            int jj = k >> 2;
            float4 v = make_float4(0.f, 0.f, 0.f, 0.f);
            if (jj < P) v = embB[(size_t)g_cpidx[b*CPBUF + jj] * 4 + (k & 3)];
            s_tab[k] = v;
        }
        __syncthreads();

        int i = half * 256 + t;
        float acc = 0.f;
        if (i < P) {
            float4 a0 = s_tab[i*4+0], a1 = s_tab[i*4+1], a2 = s_tab[i*4+2], a3 = s_tab[i*4+3];
            #pragma unroll 2
            for (int j = 0; j < P; j++) {
                float d = dist16(a0, a1, a2, a3,
                                 s_tab[j*4+0], s_tab[j*4+1], s_tab[j*4+2], s_tab[j*4+3]);
                if (d < 30.f) acc += __expf(-d);   // exp(-30)~9e-14 negligible
            }
        }
        for (int o = 16; o > 0; o >>= 1) acc += __shfl_down_sync(0xffffffffu, acc, o);
        __shared__ float wsum[8];
        if ((t & 31) == 0) wsum[t >> 5] = acc;
        __syncthreads();
        if (t < 8) {
            float v = wsum[t];
            for (int o = 4; o > 0; o >>= 1) v += __shfl_down_sync(0xffu, v, o);
            if (t == 0 && v != 0.f) atomicAdd(&g_rep[b], v);
        }
    }
}

// ---------------- finalize: 1 block per batch + ticket-based combine (R8-proven) ----------------
__global__ void __launch_bounds__(512)
finalize_kernel(float* __restrict__ out, int out_size) {
    int b = blockIdx.x;
    int t = threadIdx.x;
    int lane = t & 31, warp = t >> 5;
    __shared__ float s_rce[16], s_rat[16];
    __shared__ int   s_rvl[16];
    __shared__ bool  s_last;

    int gi = b * KK + t;          // one segment per thread
    float4 a  = g_acc[gi];
    int   cpc = g_cpcnt[gi];
    float cpb = g_cpbeta[gi];
    float ce = 0.f, at = 0.f; int vl = 0;
    if (a.x > 0.f && cpc == 1) { ce = __logf(fmaxf(a.y, 1e-30f)) - cpb; vl = 1; }
    if (a.x > 0.f && cpc >= 1)   at = __fdividef(a.z, fmaxf(a.x, 1.f));

    // reset scratch slice for next graph replay
    g_acc[gi] = make_float4(0.f, 0.f, 0.f, 0.f);
    g_cpcnt[gi] = 0; g_cpbeta[gi] = 0.f; g_fimax[gi] = 0;

    #pragma unroll
    for (int o = 16; o > 0; o >>= 1) {
        ce += __shfl_down_sync(0xffffffffu, ce, o);
        at += __shfl_down_sync(0xffffffffu, at, o);
        vl += __shfl_down_sync(0xffffffffu, vl, o);
    }
    if (lane == 0) { s_rce[warp] = ce; s_rat[warp] = at; s_rvl[warp] = vl; }
    __syncthreads();
    if (t == 0) {
        float c2 = 0.f, a2 = 0.f; int v2 = 0;
        #pragma unroll
        for (int w = 0; w < 16; w++) { c2 += s_rce[w]; a2 += s_rat[w]; v2 += s_rvl[w]; }
        float bl = c2 / fmaxf((float)v2, 1.f);
        float nbg = (float)g_nbg[b];
        if (nbg > 0.f) bl += BG_W * (g_bgsig[b] / nbg);
        float ncp = (float)g_ncp[b];
        float rep = (ncp > 1.f) ? g_rep[b] / fmaxf(ncp * ncp, 1.f) : 0.f;
        g_batch[b*5 + 0] = bl + a2 + rep;
        g_batch[b*5 + 1] = bl;
        g_batch[b*5 + 2] = a2;
        g_batch[b*5 + 3] = rep;
        g_batch[b*5 + 4] = (v2 > 0) ? 1.f : 0.f;
        g_ncp[b] = 0; g_nbg[b] = 0; g_bgsig[b] = 0.f; g_rep[b] = 0.f;
        __threadfence();
        unsigned tk = atomicAdd(&g_tick, 1u);
        s_last = (tk == BB - 1);
    }
    __syncthreads();
    if (s_last && t == 0) {
        __threadfence();
        float cnt2 = 0.f, t0 = 0.f, t1 = 0.f, t2 = 0.f, t3 = 0.f;
        for (int bb = 0; bb < BB; bb++) {
            float inc = g_batch[bb*5 + 4];
            cnt2 += inc;
            t0 += g_batch[bb*5 + 0] * inc;
            t1 += g_batch[bb*5 + 1] * inc;
            t2 += g_batch[bb*5 + 2] * inc;
            t3 += g_batch[bb*5 + 3] * inc;
        }
        float den = fmaxf(cnt2, 1.f);
        if (out_size > 0) out[0] = (cnt2 > 0.f) ? t0 / den : 0.f;
        if (out_size > 1) out[1] = t1 / den;
        if (out_size > 2) out[2] = t2 / den;
        if (out_size > 3) out[3] = t3 / den;
        g_tick = 0u;
    }
}

extern "C" void kernel_launch(void* const* d_in, const int* in_sizes, int n_in,
                              void* d_out, int out_size) {
    const float* beta  = (const float*)d_in[0];
    const float* embed = (const float*)d_in[1];
    const int*   sid   = (const int*)d_in[2];
    const int*   iscp  = (const int*)d_in[3];
    int N = in_sizes[0] / BB;

    dim3 ga(48, BB);
    pass_a<<<ga, TPB>>>(beta, sid, iscp, N);
    gather_ref<<<(BB*KK*4 + 511) / 512, 512>>>(embed, N);
    int NC = (N + PPC - 1) / PPC;
    dim3 gc(NC + 2, BB);
    pass_c<<<gc, TPB>>>(beta, embed, sid, N, NC);
    finalize_kernel<<<BB, 512>>>((float*)d_out, out_size);
}